// round 2
// baseline (speedup 1.0000x reference)
#include <cuda_runtime.h>

// Problem constants
constexpr int Bb = 64;
constexpr int Ll = 1024;
constexpr int Hh = 512;
constexpr int Tt = 100;
constexpr int Cc = 97;

// Scratch (device globals; no allocations allowed)
__device__ float g_scores[(size_t)Bb * Tt * Ll];    // [B, T, L]
__device__ float g_context[(size_t)Bb * Tt * Hh];   // [B, T, H]

#define BM 128
#define BN 128
#define BK 16
#define TM 8
#define TN 8

// C[m, n] = sum_k A[m, k] * B'[., .] (+ bias[n])
//   A is always K-major (lda = K).
//   If B_KMAJOR: B[n, k], ldb = K (dot of rows).
//   Else:        B[k, n], ldb = N (N contiguous).
// Batched over blockIdx.z with element strides.
template <bool B_KMAJOR, bool HAS_BIAS>
__global__ __launch_bounds__(256, 2)
void gemm_tn(const float* __restrict__ A,
             const float* __restrict__ Bm,
             float* __restrict__ C,
             const float* __restrict__ bias,
             int M, int N, int K,
             long long strideA, long long strideB, long long strideC)
{
    __shared__ float As[BK][BM];
    __shared__ float Bs[BK][BN];

    const int b = blockIdx.z;
    A  += (long long)b * strideA;
    Bm += (long long)b * strideB;
    C  += (long long)b * strideC;

    const int m0 = blockIdx.y * BM;
    const int n0 = blockIdx.x * BN;
    const int tid = threadIdx.x;
    const int tx = tid % 16;   // column group
    const int ty = tid / 16;   // row group

    float acc[TM][TN];
#pragma unroll
    for (int i = 0; i < TM; i++)
#pragma unroll
        for (int j = 0; j < TN; j++) acc[i][j] = 0.0f;

    for (int k0 = 0; k0 < K; k0 += BK) {
        // ---- Load A tile (K-major): 128 rows x 16 k, 512 float4, 2 per thread
#pragma unroll
        for (int i = 0; i < 2; i++) {
            int v = tid + i * 256;
            int row = v >> 2;        // 0..127
            int c4  = v & 3;         // 0..3 (k quad)
            int m = m0 + row;
            float4 val = make_float4(0.f, 0.f, 0.f, 0.f);
            if (m < M)
                val = *(const float4*)(A + (long long)m * K + k0 + c4 * 4);
            As[c4 * 4 + 0][row] = val.x;
            As[c4 * 4 + 1][row] = val.y;
            As[c4 * 4 + 2][row] = val.z;
            As[c4 * 4 + 3][row] = val.w;
        }
        // ---- Load B tile
        if (B_KMAJOR) {
#pragma unroll
            for (int i = 0; i < 2; i++) {
                int v = tid + i * 256;
                int row = v >> 2;    // n within tile
                int c4  = v & 3;
                int n = n0 + row;
                float4 val = make_float4(0.f, 0.f, 0.f, 0.f);
                if (n < N)
                    val = *(const float4*)(Bm + (long long)n * K + k0 + c4 * 4);
                Bs[c4 * 4 + 0][row] = val.x;
                Bs[c4 * 4 + 1][row] = val.y;
                Bs[c4 * 4 + 2][row] = val.z;
                Bs[c4 * 4 + 3][row] = val.w;
            }
        } else {
            // B[k, n], ldb = N; 16 rows x 128 cols
#pragma unroll
            for (int i = 0; i < 2; i++) {
                int v = tid + i * 256;
                int kk = v >> 5;     // 0..15
                int c4 = v & 31;     // 0..31 (float4 along n)
                float4 val = *(const float4*)(Bm + (long long)(k0 + kk) * N + n0 + c4 * 4);
                *(float4*)&Bs[kk][c4 * 4] = val;
            }
        }
        __syncthreads();

#pragma unroll
        for (int kk = 0; kk < BK; kk++) {
            float af[TM], bf[TN];
            *(float4*)&af[0] = *(const float4*)&As[kk][ty * TM];
            *(float4*)&af[4] = *(const float4*)&As[kk][ty * TM + 4];
            *(float4*)&bf[0] = *(const float4*)&Bs[kk][tx * TN];
            *(float4*)&bf[4] = *(const float4*)&Bs[kk][tx * TN + 4];
#pragma unroll
            for (int i = 0; i < TM; i++)
#pragma unroll
                for (int j = 0; j < TN; j++)
                    acc[i][j] = fmaf(af[i], bf[j], acc[i][j]);
        }
        __syncthreads();
    }

    // ---- Store
#pragma unroll
    for (int i = 0; i < TM; i++) {
        int m = m0 + ty * TM + i;
        if (m < M) {
#pragma unroll
            for (int j = 0; j < TN; j++) {
                int n = n0 + tx * TN + j;
                if (n < N) {
                    float o = acc[i][j];
                    if (HAS_BIAS) o += bias[n];
                    C[(long long)m * N + n] = o;
                }
            }
        }
    }
}

// Softmax over 1024 contiguous elements per row; one block per row, 256 threads.
__global__ __launch_bounds__(256)
void softmax1024(float* __restrict__ data)
{
    const long long row = blockIdx.x;
    float* p = data + row * 1024;
    const int tid = threadIdx.x;

    float4 v = ((const float4*)p)[tid];

    // max reduce
    float mx = fmaxf(fmaxf(v.x, v.y), fmaxf(v.z, v.w));
#pragma unroll
    for (int o = 16; o > 0; o >>= 1)
        mx = fmaxf(mx, __shfl_xor_sync(0xffffffffu, mx, o));

    __shared__ float red[8];
    if ((tid & 31) == 0) red[tid >> 5] = mx;
    __syncthreads();
    float mall = red[0];
#pragma unroll
    for (int i = 1; i < 8; i++) mall = fmaxf(mall, red[i]);
    __syncthreads();

    float4 e;
    e.x = expf(v.x - mall);
    e.y = expf(v.y - mall);
    e.z = expf(v.z - mall);
    e.w = expf(v.w - mall);

    float s = e.x + e.y + e.z + e.w;
#pragma unroll
    for (int o = 16; o > 0; o >>= 1)
        s += __shfl_xor_sync(0xffffffffu, s, o);
    if ((tid & 31) == 0) red[tid >> 5] = s;
    __syncthreads();
    float sall = 0.0f;
#pragma unroll
    for (int i = 0; i < 8; i++) sall += red[i];

    float inv = 1.0f / sall;
    e.x *= inv; e.y *= inv; e.z *= inv; e.w *= inv;
    ((float4*)p)[tid] = e;
}

extern "C" void kernel_launch(void* const* d_in, const int* in_sizes, int n_in,
                              void* d_out, int out_size)
{
    const float* pf   = (const float*)d_in[0];  // position_fmap [B, L, H]
    const float* of   = (const float*)d_in[1];  // origin_fmap   [B, L, H]
    const float* emb  = (const float*)d_in[2];  // pos_emb       [T, H]
    const float* W    = (const float*)d_in[3];  // W_gen         [C, H]
    const float* bias = (const float*)d_in[4];  // b_gen         [C]
    float* out = (float*)d_out;                 // [B, T, C]

    float* scores = nullptr;
    float* context = nullptr;
    cudaGetSymbolAddress((void**)&scores, g_scores);
    cudaGetSymbolAddress((void**)&context, g_context);

    // K1: scores[b, t, l] = sum_h emb[t, h] * pf[b, l, h]
    //     A = emb (M=T, K=H, K-major, batch-stride 0)
    //     B = pf[b] (N=L rows, K-major)
    {
        dim3 grid(Ll / BN, (Tt + BM - 1) / BM, Bb);
        gemm_tn<true, false><<<grid, 256>>>(
            emb, pf, scores, nullptr,
            Tt, Ll, Hh,
            0LL, (long long)Ll * Hh, (long long)Tt * Ll);
    }

    // K2: softmax over L per (b, t) row
    softmax1024<<<Bb * Tt, 256>>>(scores);

    // K3: context[b, t, h] = sum_l attn[b, t, l] * of[b, l, h]
    //     A = attn[b] (M=T, K=L, K-major)
    //     B = of[b]   (K=L rows, N=H contiguous)
    {
        dim3 grid(Hh / BN, (Tt + BM - 1) / BM, Bb);
        gemm_tn<false, false><<<grid, 256>>>(
            scores, of, context, nullptr,
            Tt, Hh, Ll,
            (long long)Tt * Ll, (long long)Ll * Hh, (long long)Tt * Hh);
    }

    // K4: out[bt, c] = sum_h context[bt, h] * W[c, h] + bias[c]
    {
        dim3 grid((Cc + BN - 1) / BN, (Bb * Tt) / BM, 1);
        gemm_tn<true, true><<<grid, 256>>>(
            context, W, out, bias,
            Bb * Tt, Cc, Hh,
            0LL, 0LL, 0LL);
    }
}

// round 4
// speedup vs baseline: 1.9227x; 1.9227x over previous
#include <cuda_runtime.h>
#include <cuda_bf16.h>
#include <cstdint>

constexpr int Bb = 64;
constexpr int Ll = 1024;
constexpr int Hh = 512;
constexpr int Tt = 100;
constexpr int Cc = 97;

// Scratch (device globals; no allocations allowed)
__device__ float g_scores[(size_t)Bb * Tt * Ll];    // [B, T, L]
__device__ float g_context[(size_t)Bb * Tt * Hh];   // [B, T, H]

__device__ __forceinline__ uint32_t smem_u32(const void* p) {
    uint32_t a;
    asm("{ .reg .u64 t; cvta.to.shared.u64 t, %1; cvt.u32.u64 %0, t; }"
        : "=r"(a) : "l"(p));
    return a;
}

__device__ __forceinline__ uint32_t bpack(__nv_bfloat16 a, __nv_bfloat16 b) {
    __nv_bfloat162 t;
    t.x = a; t.y = b;
    return reinterpret_cast<uint32_t&>(t);
}

__device__ __forceinline__ void split2(float x, __nv_bfloat16& h, __nv_bfloat16& l) {
    h = __float2bfloat16(x);
    l = __float2bfloat16(x - __bfloat162float(h));
}

__device__ __forceinline__ void ldmx4(uint32_t* r, uint32_t addr) {
    asm volatile("ldmatrix.sync.aligned.m8n8.x4.shared.b16 {%0,%1,%2,%3}, [%4];"
                 : "=r"(r[0]), "=r"(r[1]), "=r"(r[2]), "=r"(r[3]) : "r"(addr));
}

__device__ __forceinline__ void mma16816(float* c, const uint32_t* a,
                                         uint32_t b0, uint32_t b1) {
    asm volatile(
        "mma.sync.aligned.m16n8k16.row.col.f32.bf16.bf16.f32 "
        "{%0,%1,%2,%3}, {%4,%5,%6,%7}, {%8,%9}, {%0,%1,%2,%3};"
        : "+f"(c[0]), "+f"(c[1]), "+f"(c[2]), "+f"(c[3])
        : "r"(a[0]), "r"(a[1]), "r"(a[2]), "r"(a[3]), "r"(b0), "r"(b1));
}

// ---------------------------------------------------------------------------
// HMMA GEMM: C[M, N] = A[M, K] @ B^T (+ bias), fp32 in/out, bf16 3-split.
//   A: [m, k] K-major, lda; rows >= M_real read as 0.
//   B (!B_TRANS): [n, k] K-major, ldb; rows >= N_real read as 0.
//   B (B_TRANS):  global [k, n], row stride ldb; assumed full tile (K3 only).
// CTA tile 128x128, 256 threads (8 warps, each 64x32), K chunk = 32 fp32.
// ---------------------------------------------------------------------------
template <bool B_TRANS, bool HAS_BIAS>
__global__ __launch_bounds__(256)
void hmma_gemm(const float* __restrict__ A, const float* __restrict__ Bg,
               float* __restrict__ C, const float* __restrict__ bias,
               int M_real, int N_real, int K,
               int lda, int ldb, int ldc,
               long long sA, long long sB, long long sC)
{
    extern __shared__ char smem[];
    // bf16 tiles: 128 rows x 32 k, row stride 80 bytes (64 data + 16 pad)
    constexpr int ROWB = 80;
    constexpr int A_HI = 0;
    constexpr int A_LO = 128 * ROWB;          // 10240
    constexpr int B_HI = 2 * 128 * ROWB;      // 20480
    constexpr int B_LO = 3 * 128 * ROWB;      // 30720
    constexpr int STAGE = 4 * 128 * ROWB;     // 40960 (fp32 stage, B_TRANS only)
    constexpr int STG_STRIDE = 132;           // floats per k-row (128 + 4 pad)

    float* stage = (float*)(smem + STAGE);
    const uint32_t sb = smem_u32(smem);

    const int b = blockIdx.z;
    A  += (long long)b * sA;
    Bg += (long long)b * sB;
    C  += (long long)b * sC;

    const int m0 = blockIdx.y * 128;
    const int n0 = blockIdx.x * 128;
    const int tid = threadIdx.x;
    const int lane = tid & 31;
    const int wid = tid >> 5;
    const int wm = wid & 1;        // 2 warp-rows of 64
    const int wn = wid >> 1;       // 4 warp-cols of 32
    const int gid = lane >> 2;
    const int tig = lane & 3;

    // ldmatrix per-thread base addresses
    const uint32_t pA = sb + (uint32_t)((wm * 64 + (lane & 15)) * ROWB + (lane >> 4) * 16);
    const uint32_t pB = sb + (uint32_t)((wn * 32 + (lane & 7) + ((lane >> 4) & 1) * 8) * ROWB
                                        + ((lane >> 3) & 1) * 16);

    float acc[4][4][4];
#pragma unroll
    for (int i = 0; i < 4; i++)
#pragma unroll
        for (int j = 0; j < 4; j++)
#pragma unroll
            for (int k = 0; k < 4; k++) acc[i][j][k] = 0.0f;

    const int nchunks = K >> 5;
#pragma unroll 1
    for (int c = 0; c < nchunks; ++c) {
        const int kc = c << 5;

        // ---- A tile: 128 rows x 32 k fp32 -> hi/lo bf16
#pragma unroll
        for (int i = 0; i < 4; ++i) {
            int v = i * 256 + tid;
            int row = v >> 3, q = v & 7;
            int m = m0 + row;
            float4 x = make_float4(0.f, 0.f, 0.f, 0.f);
            if (m < M_real)
                x = *(const float4*)(A + (long long)m * lda + kc + q * 4);
            __nv_bfloat16 h0, h1, h2, h3, l0, l1, l2, l3;
            split2(x.x, h0, l0); split2(x.y, h1, l1);
            split2(x.z, h2, l2); split2(x.w, h3, l3);
            int off = row * ROWB + q * 8;
            *(uint2*)(smem + A_HI + off) = make_uint2(bpack(h0, h1), bpack(h2, h3));
            *(uint2*)(smem + A_LO + off) = make_uint2(bpack(l0, l1), bpack(l2, l3));
        }

        // ---- B tile
        if (!B_TRANS) {
#pragma unroll
            for (int i = 0; i < 4; ++i) {
                int v = i * 256 + tid;
                int row = v >> 3, q = v & 7;
                int n = n0 + row;
                float4 x = make_float4(0.f, 0.f, 0.f, 0.f);
                if (n < N_real)
                    x = *(const float4*)(Bg + (long long)n * ldb + kc + q * 4);
                __nv_bfloat16 h0, h1, h2, h3, l0, l1, l2, l3;
                split2(x.x, h0, l0); split2(x.y, h1, l1);
                split2(x.z, h2, l2); split2(x.w, h3, l3);
                int off = row * ROWB + q * 8;
                *(uint2*)(smem + B_HI + off) = make_uint2(bpack(h0, h1), bpack(h2, h3));
                *(uint2*)(smem + B_LO + off) = make_uint2(bpack(l0, l1), bpack(l2, l3));
            }
        } else {
            // stage 32 k-rows x 128 n fp32 (coalesced), then transpose-convert
#pragma unroll
            for (int i = 0; i < 4; ++i) {
                int v = i * 256 + tid;
                int r = v >> 5, c4 = v & 31;
                float4 x = *(const float4*)(Bg + (long long)(kc + r) * ldb + n0 + c4 * 4);
                *(float4*)(stage + r * STG_STRIDE + c4 * 4) = x;
            }
            __syncthreads();
            {
                int n = tid & 127;
                int kh = tid >> 7;           // 0/1 -> k 0..15 / 16..31
#pragma unroll
                for (int j = 0; j < 4; ++j) {
                    float v0 = stage[(kh * 16 + j * 4 + 0) * STG_STRIDE + n];
                    float v1 = stage[(kh * 16 + j * 4 + 1) * STG_STRIDE + n];
                    float v2 = stage[(kh * 16 + j * 4 + 2) * STG_STRIDE + n];
                    float v3 = stage[(kh * 16 + j * 4 + 3) * STG_STRIDE + n];
                    __nv_bfloat16 h0, h1, h2, h3, l0, l1, l2, l3;
                    split2(v0, h0, l0); split2(v1, h1, l1);
                    split2(v2, h2, l2); split2(v3, h3, l3);
                    int off = n * ROWB + kh * 32 + j * 8;
                    *(uint2*)(smem + B_HI + off) = make_uint2(bpack(h0, h1), bpack(h2, h3));
                    *(uint2*)(smem + B_LO + off) = make_uint2(bpack(l0, l1), bpack(l2, l3));
                }
            }
        }
        __syncthreads();

        // ---- MMA: 2 k16-steps, 3 split products
#pragma unroll
        for (int ks = 0; ks < 2; ++ks) {
            uint32_t ahi[4][4], alo[4][4], bhi[2][4], blo[2][4];
#pragma unroll
            for (int mi = 0; mi < 4; ++mi) {
                ldmx4(ahi[mi], pA + A_HI + mi * (16 * ROWB) + ks * 32);
                ldmx4(alo[mi], pA + A_LO + mi * (16 * ROWB) + ks * 32);
            }
#pragma unroll
            for (int nj = 0; nj < 2; ++nj) {
                ldmx4(bhi[nj], pB + B_HI + nj * (16 * ROWB) + ks * 32);
                ldmx4(blo[nj], pB + B_LO + nj * (16 * ROWB) + ks * 32);
            }
#pragma unroll
            for (int mi = 0; mi < 4; ++mi) {
#pragma unroll
                for (int nt = 0; nt < 4; ++nt) {
                    int hj = nt >> 1, hk = (nt & 1) * 2;
                    mma16816(acc[mi][nt], ahi[mi], bhi[hj][hk], bhi[hj][hk + 1]);
                    mma16816(acc[mi][nt], ahi[mi], blo[hj][hk], blo[hj][hk + 1]);
                    mma16816(acc[mi][nt], alo[mi], bhi[hj][hk], bhi[hj][hk + 1]);
                }
            }
        }
        __syncthreads();
    }

    // ---- Epilogue
#pragma unroll
    for (int mi = 0; mi < 4; ++mi) {
#pragma unroll
        for (int nt = 0; nt < 4; ++nt) {
            int r0 = m0 + wm * 64 + mi * 16 + gid;
            int cb = n0 + wn * 32 + nt * 8 + tig * 2;
#pragma unroll
            for (int half = 0; half < 2; ++half) {
                int r = r0 + half * 8;
                if (r < M_real) {
                    float v0 = acc[mi][nt][half * 2 + 0];
                    float v1 = acc[mi][nt][half * 2 + 1];
                    if (cb < N_real) {
                        float o = v0;
                        if (HAS_BIAS) o += bias[cb];
                        C[(long long)r * ldc + cb] = o;
                    }
                    if (cb + 1 < N_real) {
                        float o = v1;
                        if (HAS_BIAS) o += bias[cb + 1];
                        C[(long long)r * ldc + cb + 1] = o;
                    }
                }
            }
        }
    }
}

// ---------------------------------------------------------------------------
// Softmax over 1024 contiguous elements per row; one block per row.
// ---------------------------------------------------------------------------
__global__ __launch_bounds__(256)
void softmax1024(float* __restrict__ data)
{
    const long long row = blockIdx.x;
    float* p = data + row * 1024;
    const int tid = threadIdx.x;

    float4 v = ((const float4*)p)[tid];
    float mx = fmaxf(fmaxf(v.x, v.y), fmaxf(v.z, v.w));
#pragma unroll
    for (int o = 16; o > 0; o >>= 1)
        mx = fmaxf(mx, __shfl_xor_sync(0xffffffffu, mx, o));

    __shared__ float red[8];
    if ((tid & 31) == 0) red[tid >> 5] = mx;
    __syncthreads();
    float mall = red[0];
#pragma unroll
    for (int i = 1; i < 8; i++) mall = fmaxf(mall, red[i]);
    __syncthreads();

    float4 e;
    e.x = expf(v.x - mall); e.y = expf(v.y - mall);
    e.z = expf(v.z - mall); e.w = expf(v.w - mall);

    float s = e.x + e.y + e.z + e.w;
#pragma unroll
    for (int o = 16; o > 0; o >>= 1)
        s += __shfl_xor_sync(0xffffffffu, s, o);
    if ((tid & 31) == 0) red[tid >> 5] = s;
    __syncthreads();
    float sall = 0.0f;
#pragma unroll
    for (int i = 0; i < 8; i++) sall += red[i];

    float inv = 1.0f / sall;
    e.x *= inv; e.y *= inv; e.z *= inv; e.w *= inv;
    ((float4*)p)[tid] = e;
}

// ---------------------------------------------------------------------------
extern "C" void kernel_launch(void* const* d_in, const int* in_sizes, int n_in,
                              void* d_out, int out_size)
{
    const float* pf   = (const float*)d_in[0];  // position_fmap [B, L, H]
    const float* of   = (const float*)d_in[1];  // origin_fmap   [B, L, H]
    const float* emb  = (const float*)d_in[2];  // pos_emb       [T, H]
    const float* W    = (const float*)d_in[3];  // W_gen         [C, H]
    const float* bias = (const float*)d_in[4];  // b_gen         [C]
    float* out = (float*)d_out;                 // [B, T, C]

    float* scores = nullptr;
    float* context = nullptr;
    cudaGetSymbolAddress((void**)&scores, g_scores);
    cudaGetSymbolAddress((void**)&context, g_context);

    constexpr int SMEM_STD = 4 * 128 * 80;                    // 40960
    constexpr int SMEM_TRA = 4 * 128 * 80 + 32 * 132 * 4;     // 57856
    cudaFuncSetAttribute((const void*)hmma_gemm<false, false>,
                         cudaFuncAttributeMaxDynamicSharedMemorySize, SMEM_STD);
    cudaFuncSetAttribute((const void*)hmma_gemm<true, false>,
                         cudaFuncAttributeMaxDynamicSharedMemorySize, SMEM_TRA);
    cudaFuncSetAttribute((const void*)hmma_gemm<false, true>,
                         cudaFuncAttributeMaxDynamicSharedMemorySize, SMEM_STD);

    // K1: scores[b, t, l] = sum_h emb[t, h] * pf[b, l, h]
    {
        dim3 grid(Ll / 128, 1, Bb);
        hmma_gemm<false, false><<<grid, 256, SMEM_STD>>>(
            emb, pf, scores, nullptr,
            Tt, Ll, Hh,
            Hh, Hh, Ll,
            0LL, (long long)Ll * Hh, (long long)Tt * Ll);
    }

    // K2: softmax over L per (b, t) row
    softmax1024<<<Bb * Tt, 256>>>(scores);

    // K3: context[b, t, h] = sum_l attn[b, t, l] * of[b, l, h]
    {
        dim3 grid(Hh / 128, 1, Bb);
        hmma_gemm<true, false><<<grid, 256, SMEM_TRA>>>(
            scores, of, context, nullptr,
            Tt, Hh, Ll,
            Ll, Hh, Hh,
            (long long)Tt * Ll, (long long)Ll * Hh, (long long)Tt * Hh);
    }

    // K4: out[bt, c] = sum_h context[bt, h] * W[c, h] + bias[c]
    {
        dim3 grid(1, (Bb * Tt) / 128, 1);
        hmma_gemm<false, true><<<grid, 256, SMEM_STD>>>(
            context, W, out, bias,
            Bb * Tt, Cc, Hh,
            Hh, Hh, Cc,
            0LL, 0LL, 0LL);
    }
}

// round 5
// speedup vs baseline: 2.6670x; 1.3871x over previous
#include <cuda_runtime.h>
#include <cuda_bf16.h>
#include <cstdint>

constexpr int Bb = 64;
constexpr int Ll = 1024;
constexpr int Hh = 512;
constexpr int Tt = 100;
constexpr int Cc = 97;

// Scratch (device globals; no allocations allowed)
__device__ float g_scores[(size_t)Bb * Tt * Ll];    // [B, T, L]
__device__ float g_context[(size_t)Bb * Tt * Hh];   // [B, T, H]

__device__ __forceinline__ uint32_t smem_u32(const void* p) {
    uint32_t a;
    asm("{ .reg .u64 t; cvta.to.shared.u64 t, %1; cvt.u32.u64 %0, t; }"
        : "=r"(a) : "l"(p));
    return a;
}

// hi = top-16-bits-truncated bf16 of x; pack two his with one PRMT
__device__ __forceinline__ uint32_t hi_pack(float x0, float x1) {
    return __byte_perm(__float_as_uint(x0), __float_as_uint(x1), 0x7632);
}
__device__ __forceinline__ float trunc_hi(float x) {
    return __uint_as_float(__float_as_uint(x) & 0xffff0000u);
}
__device__ __forceinline__ uint32_t lo_pack(float l0, float l1) {
    uint32_t r;
    asm("cvt.rn.bf16x2.f32 %0, %1, %2;" : "=r"(r) : "f"(l1), "f"(l0));
    return r;
}
// float4 -> packed hi (uint2) + packed lo (uint2)
__device__ __forceinline__ void cvt4(float4 x, uint2& h, uint2& l) {
    h.x = hi_pack(x.x, x.y);
    h.y = hi_pack(x.z, x.w);
    l.x = lo_pack(x.x - trunc_hi(x.x), x.y - trunc_hi(x.y));
    l.y = lo_pack(x.z - trunc_hi(x.z), x.w - trunc_hi(x.w));
}

__device__ __forceinline__ void ldmx4(uint32_t* r, uint32_t addr) {
    asm volatile("ldmatrix.sync.aligned.m8n8.x4.shared.b16 {%0,%1,%2,%3}, [%4];"
                 : "=r"(r[0]), "=r"(r[1]), "=r"(r[2]), "=r"(r[3]) : "r"(addr));
}
__device__ __forceinline__ void ldmx4t(uint32_t* r, uint32_t addr) {
    asm volatile("ldmatrix.sync.aligned.m8n8.x4.trans.shared.b16 {%0,%1,%2,%3}, [%4];"
                 : "=r"(r[0]), "=r"(r[1]), "=r"(r[2]), "=r"(r[3]) : "r"(addr));
}

__device__ __forceinline__ void mma16816(float* c, const uint32_t* a,
                                         uint32_t b0, uint32_t b1) {
    asm volatile(
        "mma.sync.aligned.m16n8k16.row.col.f32.bf16.bf16.f32 "
        "{%0,%1,%2,%3}, {%4,%5,%6,%7}, {%8,%9}, {%0,%1,%2,%3};"
        : "+f"(c[0]), "+f"(c[1]), "+f"(c[2]), "+f"(c[3])
        : "r"(a[0]), "r"(a[1]), "r"(a[2]), "r"(a[3]), "r"(b0), "r"(b1));
}

// ---------------------------------------------------------------------------
// HMMA GEMM, fp32 in/out via bf16 3-split, software-pipelined.
//   BMODE 0: B is [n, k] K-major (ldb = row stride); rows >= N_real read 0.
//   BMODE 1: B is [k, n] row-major (ldb = row stride); full tile assumed (K3).
// CTA tile 128x128, 256 threads (8 warps, 2x4, warp tile 64x32), K chunk 32.
// ---------------------------------------------------------------------------
template <int BMODE, bool HAS_BIAS>
__global__ __launch_bounds__(256, 1)
void hmma_gemm(const float* __restrict__ A, const float* __restrict__ Bg,
               float* __restrict__ C, const float* __restrict__ bias,
               int M_real, int N_real, int K,
               int lda, int ldb, int ldc,
               long long sA, long long sB, long long sC)
{
    extern __shared__ char smem[];
    constexpr int ROWB  = 80;                         // A row stride (64B data + 16 pad)
    constexpr int ATILE = 128 * ROWB;                 // 10240
    constexpr int BROWB = (BMODE == 0) ? 80 : 272;    // mode1: 256B data + 16 pad
    constexpr int BTILE = (BMODE == 0) ? 128 * 80 : 32 * 272;
    constexpr int BUFSZ = 2 * ATILE + 2 * BTILE;
    // per-buffer layout: [A_HI][A_LO][B_HI][B_LO]

    const uint32_t sb = smem_u32(smem);

    const int b = blockIdx.z;
    A  += (long long)b * sA;
    Bg += (long long)b * sB;
    C  += (long long)b * sC;

    const int m0 = blockIdx.y * 128;
    const int n0 = blockIdx.x * 128;
    const int tid = threadIdx.x;
    const int lane = tid & 31;
    const int wid = tid >> 5;
    const int wm = wid & 1;
    const int wn = wid >> 1;
    const int gid = lane >> 2;
    const int tig = lane & 3;

    // ldmatrix lane address components (relative to tile bases)
    const uint32_t offA = (uint32_t)((wm * 64 + (lane & 15)) * ROWB + (lane >> 4) * 16);
    const uint32_t offB0 = (uint32_t)((wn * 32 + (lane & 7) + ((lane >> 4) & 1) * 8) * 80
                                      + ((lane >> 3) & 1) * 16);            // mode0
    const uint32_t offB1 = (uint32_t)(((lane & 7) + 8 * ((lane >> 3) & 1)) * 272
                                      + (wn * 32 + ((lane >> 4) & 1) * 8) * 2); // mode1

    float acc[4][4][4];
#pragma unroll
    for (int i = 0; i < 4; i++)
#pragma unroll
        for (int j = 0; j < 4; j++)
#pragma unroll
            for (int k = 0; k < 4; k++) acc[i][j][k] = 0.0f;

    float4 ar[4], br[4];

    auto loadA = [&](int kc) {
#pragma unroll
        for (int i = 0; i < 4; ++i) {
            int v = i * 256 + tid;
            int row = v >> 3, q = v & 7;
            int m = m0 + row;
            ar[i] = make_float4(0.f, 0.f, 0.f, 0.f);
            if (m < M_real)
                ar[i] = *(const float4*)(A + (long long)m * lda + kc + q * 4);
        }
    };
    auto loadB = [&](int kc) {
        if (BMODE == 0) {
#pragma unroll
            for (int i = 0; i < 4; ++i) {
                int v = i * 256 + tid;
                int row = v >> 3, q = v & 7;
                int n = n0 + row;
                br[i] = make_float4(0.f, 0.f, 0.f, 0.f);
                if (n < N_real)
                    br[i] = *(const float4*)(Bg + (long long)n * ldb + kc + q * 4);
            }
        } else {
#pragma unroll
            for (int i = 0; i < 4; ++i) {
                int v = i * 256 + tid;
                int r = v >> 5, c4 = v & 31;
                br[i] = *(const float4*)(Bg + (long long)(kc + r) * ldb + n0 + c4 * 4);
            }
        }
    };
    auto storeTiles = [&](int buf) {
        char* base = smem + buf * BUFSZ;
#pragma unroll
        for (int i = 0; i < 4; ++i) {
            int v = i * 256 + tid;
            int row = v >> 3, q = v & 7;
            uint2 h, l;
            cvt4(ar[i], h, l);
            *(uint2*)(base + row * ROWB + q * 8) = h;
            *(uint2*)(base + ATILE + row * ROWB + q * 8) = l;
        }
        if (BMODE == 0) {
#pragma unroll
            for (int i = 0; i < 4; ++i) {
                int v = i * 256 + tid;
                int row = v >> 3, q = v & 7;
                uint2 h, l;
                cvt4(br[i], h, l);
                *(uint2*)(base + 2 * ATILE + row * 80 + q * 8) = h;
                *(uint2*)(base + 2 * ATILE + BTILE + row * 80 + q * 8) = l;
            }
        } else {
#pragma unroll
            for (int i = 0; i < 4; ++i) {
                int v = i * 256 + tid;
                int r = v >> 5, c4 = v & 31;
                uint2 h, l;
                cvt4(br[i], h, l);
                *(uint2*)(base + 2 * ATILE + r * 272 + c4 * 8) = h;
                *(uint2*)(base + 2 * ATILE + BTILE + r * 272 + c4 * 8) = l;
            }
        }
    };

    const int nchunks = K >> 5;
    loadA(0);
    loadB(0);

#pragma unroll 1
    for (int c = 0; c < nchunks; ++c) {
        const int buf = c & 1;
        storeTiles(buf);
        __syncthreads();

        if (c + 1 < nchunks) {
            loadA((c + 1) << 5);
            loadB((c + 1) << 5);
        }

        const uint32_t tbase = sb + buf * BUFSZ;
        const uint32_t pAhi = tbase + offA;
        const uint32_t pAlo = pAhi + ATILE;

#pragma unroll
        for (int ks = 0; ks < 2; ++ks) {
            uint32_t ahi[4][4], alo[4][4];
#pragma unroll
            for (int mi = 0; mi < 4; ++mi) {
                ldmx4(ahi[mi], pAhi + mi * (16 * ROWB) + ks * 32);
                ldmx4(alo[mi], pAlo + mi * (16 * ROWB) + ks * 32);
            }
            uint32_t bh[4][2], bl[4][2];
            if (BMODE == 0) {
                const uint32_t pBhi = tbase + 2 * ATILE + offB0;
                const uint32_t pBlo = pBhi + BTILE;
#pragma unroll
                for (int g = 0; g < 2; ++g) {
                    uint32_t t[4];
                    ldmx4(t, pBhi + g * (16 * 80) + ks * 32);
                    bh[2 * g][0] = t[0]; bh[2 * g][1] = t[1];
                    bh[2 * g + 1][0] = t[2]; bh[2 * g + 1][1] = t[3];
                    ldmx4(t, pBlo + g * (16 * 80) + ks * 32);
                    bl[2 * g][0] = t[0]; bl[2 * g][1] = t[1];
                    bl[2 * g + 1][0] = t[2]; bl[2 * g + 1][1] = t[3];
                }
            } else {
                const uint32_t pBhi = tbase + 2 * ATILE + offB1 + ks * (16 * 272);
                const uint32_t pBlo = pBhi + BTILE;
#pragma unroll
                for (int g = 0; g < 2; ++g) {
                    uint32_t t[4];
                    ldmx4t(t, pBhi + g * 32);
                    bh[2 * g][0] = t[0]; bh[2 * g][1] = t[1];
                    bh[2 * g + 1][0] = t[2]; bh[2 * g + 1][1] = t[3];
                    ldmx4t(t, pBlo + g * 32);
                    bl[2 * g][0] = t[0]; bl[2 * g][1] = t[1];
                    bl[2 * g + 1][0] = t[2]; bl[2 * g + 1][1] = t[3];
                }
            }
#pragma unroll
            for (int mi = 0; mi < 4; ++mi) {
#pragma unroll
                for (int nt = 0; nt < 4; ++nt) {
                    mma16816(acc[mi][nt], ahi[mi], bh[nt][0], bh[nt][1]);
                    mma16816(acc[mi][nt], ahi[mi], bl[nt][0], bl[nt][1]);
                    mma16816(acc[mi][nt], alo[mi], bh[nt][0], bh[nt][1]);
                }
            }
        }
        // single barrier per chunk: next iteration's convert targets the other
        // buffer; passing this iteration's barrier implies mma(c-1) finished.
    }

    // ---- Epilogue
#pragma unroll
    for (int mi = 0; mi < 4; ++mi) {
#pragma unroll
        for (int nt = 0; nt < 4; ++nt) {
            int r0 = m0 + wm * 64 + mi * 16 + gid;
            int cb = n0 + wn * 32 + nt * 8 + tig * 2;
#pragma unroll
            for (int half = 0; half < 2; ++half) {
                int r = r0 + half * 8;
                if (r < M_real) {
                    float v0 = acc[mi][nt][half * 2 + 0];
                    float v1 = acc[mi][nt][half * 2 + 1];
                    if (cb < N_real) {
                        float o = v0;
                        if (HAS_BIAS) o += bias[cb];
                        C[(long long)r * ldc + cb] = o;
                    }
                    if (cb + 1 < N_real) {
                        float o = v1;
                        if (HAS_BIAS) o += bias[cb + 1];
                        C[(long long)r * ldc + cb + 1] = o;
                    }
                }
            }
        }
    }
}

// ---------------------------------------------------------------------------
// Softmax over 1024 contiguous elements per row; one block per row.
// ---------------------------------------------------------------------------
__global__ __launch_bounds__(256)
void softmax1024(float* __restrict__ data)
{
    const long long row = blockIdx.x;
    float* p = data + row * 1024;
    const int tid = threadIdx.x;

    float4 v = ((const float4*)p)[tid];
    float mx = fmaxf(fmaxf(v.x, v.y), fmaxf(v.z, v.w));
#pragma unroll
    for (int o = 16; o > 0; o >>= 1)
        mx = fmaxf(mx, __shfl_xor_sync(0xffffffffu, mx, o));

    __shared__ float red[8];
    if ((tid & 31) == 0) red[tid >> 5] = mx;
    __syncthreads();
    float mall = red[0];
#pragma unroll
    for (int i = 1; i < 8; i++) mall = fmaxf(mall, red[i]);
    __syncthreads();

    float4 e;
    e.x = expf(v.x - mall); e.y = expf(v.y - mall);
    e.z = expf(v.z - mall); e.w = expf(v.w - mall);

    float s = e.x + e.y + e.z + e.w;
#pragma unroll
    for (int o = 16; o > 0; o >>= 1)
        s += __shfl_xor_sync(0xffffffffu, s, o);
    if ((tid & 31) == 0) red[tid >> 5] = s;
    __syncthreads();
    float sall = 0.0f;
#pragma unroll
    for (int i = 0; i < 8; i++) sall += red[i];

    float inv = 1.0f / sall;
    e.x *= inv; e.y *= inv; e.z *= inv; e.w *= inv;
    ((float4*)p)[tid] = e;
}

// ---------------------------------------------------------------------------
extern "C" void kernel_launch(void* const* d_in, const int* in_sizes, int n_in,
                              void* d_out, int out_size)
{
    const float* pf   = (const float*)d_in[0];  // position_fmap [B, L, H]
    const float* of   = (const float*)d_in[1];  // origin_fmap   [B, L, H]
    const float* emb  = (const float*)d_in[2];  // pos_emb       [T, H]
    const float* W    = (const float*)d_in[3];  // W_gen         [C, H]
    const float* bias = (const float*)d_in[4];  // b_gen         [C]
    float* out = (float*)d_out;                 // [B, T, C]

    float* scores = nullptr;
    float* context = nullptr;
    cudaGetSymbolAddress((void**)&scores, g_scores);
    cudaGetSymbolAddress((void**)&context, g_context);

    constexpr int SMEM0 = 2 * (2 * 128 * 80 + 2 * 128 * 80);   // 81920
    constexpr int SMEM1 = 2 * (2 * 128 * 80 + 2 * 32 * 272);   // 75776
    cudaFuncSetAttribute((const void*)hmma_gemm<0, false>,
                         cudaFuncAttributeMaxDynamicSharedMemorySize, SMEM0);
    cudaFuncSetAttribute((const void*)hmma_gemm<1, false>,
                         cudaFuncAttributeMaxDynamicSharedMemorySize, SMEM1);
    cudaFuncSetAttribute((const void*)hmma_gemm<0, true>,
                         cudaFuncAttributeMaxDynamicSharedMemorySize, SMEM0);

    // K1: scores[b, t, l] = sum_h emb[t, h] * pf[b, l, h]
    {
        dim3 grid(Ll / 128, 1, Bb);
        hmma_gemm<0, false><<<grid, 256, SMEM0>>>(
            emb, pf, scores, nullptr,
            Tt, Ll, Hh,
            Hh, Hh, Ll,
            0LL, (long long)Ll * Hh, (long long)Tt * Ll);
    }

    // K2: softmax over L per (b, t) row
    softmax1024<<<Bb * Tt, 256>>>(scores);

    // K3: context[b, t, h] = sum_l attn[b, t, l] * of[b, l, h]
    //     B = of[b] is [k=l, n=h] row-major -> BMODE 1 (ldmatrix.trans)
    {
        dim3 grid(Hh / 128, 1, Bb);
        hmma_gemm<1, false><<<grid, 256, SMEM1>>>(
            scores, of, context, nullptr,
            Tt, Hh, Ll,
            Ll, Hh, Hh,
            (long long)Tt * Ll, (long long)Ll * Hh, (long long)Tt * Hh);
    }

    // K4: out[bt, c] = sum_h context[bt, h] * W[c, h] + bias[c]
    {
        dim3 grid(1, (Bb * Tt) / 128, 1);
        hmma_gemm<0, true><<<grid, 256, SMEM0>>>(
            context, W, out, bias,
            Bb * Tt, Cc, Hh,
            Hh, Hh, Cc,
            0LL, 0LL, 0LL);
    }
}

// round 6
// speedup vs baseline: 2.6699x; 1.0011x over previous
#include <cuda_runtime.h>
#include <cuda_bf16.h>
#include <cstdint>

constexpr int Bb = 64;
constexpr int Ll = 1024;
constexpr int Hh = 512;
constexpr int Tt = 100;
constexpr int Cc = 97;

// Scratch (device globals; no allocations allowed)
__device__ float g_scores[(size_t)Bb * Tt * Ll];    // [B, T, L]
__device__ float g_context[(size_t)Bb * Tt * Hh];   // [B, T, H]

__device__ __forceinline__ uint32_t smem_u32(const void* p) {
    uint32_t a;
    asm("{ .reg .u64 t; cvta.to.shared.u64 t, %1; cvt.u32.u64 %0, t; }"
        : "=r"(a) : "l"(p));
    return a;
}

// hi = top-16-bits-truncated bf16 of x; pack two his with one PRMT
__device__ __forceinline__ uint32_t hi_pack(float x0, float x1) {
    return __byte_perm(__float_as_uint(x0), __float_as_uint(x1), 0x7632);
}
__device__ __forceinline__ float trunc_hi(float x) {
    return __uint_as_float(__float_as_uint(x) & 0xffff0000u);
}
__device__ __forceinline__ uint32_t lo_pack(float l0, float l1) {
    uint32_t r;
    asm("cvt.rn.bf16x2.f32 %0, %1, %2;" : "=r"(r) : "f"(l1), "f"(l0));
    return r;
}
// float4 -> packed hi (uint2) + packed lo (uint2)
__device__ __forceinline__ void cvt4(float4 x, uint2& h, uint2& l) {
    h.x = hi_pack(x.x, x.y);
    h.y = hi_pack(x.z, x.w);
    l.x = lo_pack(x.x - trunc_hi(x.x), x.y - trunc_hi(x.y));
    l.y = lo_pack(x.z - trunc_hi(x.z), x.w - trunc_hi(x.w));
}

__device__ __forceinline__ void ldmx4(uint32_t* r, uint32_t addr) {
    asm volatile("ldmatrix.sync.aligned.m8n8.x4.shared.b16 {%0,%1,%2,%3}, [%4];"
                 : "=r"(r[0]), "=r"(r[1]), "=r"(r[2]), "=r"(r[3]) : "r"(addr));
}
__device__ __forceinline__ void ldmx4t(uint32_t* r, uint32_t addr) {
    asm volatile("ldmatrix.sync.aligned.m8n8.x4.trans.shared.b16 {%0,%1,%2,%3}, [%4];"
                 : "=r"(r[0]), "=r"(r[1]), "=r"(r[2]), "=r"(r[3]) : "r"(addr));
}

__device__ __forceinline__ void mma16816(float* c, const uint32_t* a,
                                         uint32_t b0, uint32_t b1) {
    asm volatile(
        "mma.sync.aligned.m16n8k16.row.col.f32.bf16.bf16.f32 "
        "{%0,%1,%2,%3}, {%4,%5,%6,%7}, {%8,%9}, {%0,%1,%2,%3};"
        : "+f"(c[0]), "+f"(c[1]), "+f"(c[2]), "+f"(c[3])
        : "r"(a[0]), "r"(a[1]), "r"(a[2]), "r"(a[3]), "r"(b0), "r"(b1));
}

// ---------------------------------------------------------------------------
// HMMA GEMM, fp32 in/out via bf16 3-split, software-pipelined.
//   BMODE 0: B is [n, k] K-major (ldb = row stride); rows >= N_real read 0.
//   BMODE 1: B is [k, n] row-major (ldb = row stride); full tile assumed (K3).
// CTA tile 128x128, 256 threads (8 warps, 2x4, warp tile 64x32), K chunk 32.
// ---------------------------------------------------------------------------
template <int BMODE, bool HAS_BIAS>
__global__ __launch_bounds__(256, 1)
void hmma_gemm(const float* __restrict__ A, const float* __restrict__ Bg,
               float* __restrict__ C, const float* __restrict__ bias,
               int M_real, int N_real, int K,
               int lda, int ldb, int ldc,
               long long sA, long long sB, long long sC)
{
    extern __shared__ char smem[];
    constexpr int ROWB  = 80;                         // A row stride (64B data + 16 pad)
    constexpr int ATILE = 128 * ROWB;                 // 10240
    constexpr int BROWB = (BMODE == 0) ? 80 : 272;    // mode1: 256B data + 16 pad
    constexpr int BTILE = (BMODE == 0) ? 128 * 80 : 32 * 272;
    constexpr int BUFSZ = 2 * ATILE + 2 * BTILE;
    // per-buffer layout: [A_HI][A_LO][B_HI][B_LO]

    const uint32_t sb = smem_u32(smem);

    const int b = blockIdx.z;
    A  += (long long)b * sA;
    Bg += (long long)b * sB;
    C  += (long long)b * sC;

    const int m0 = blockIdx.y * 128;
    const int n0 = blockIdx.x * 128;
    const int tid = threadIdx.x;
    const int lane = tid & 31;
    const int wid = tid >> 5;
    const int wm = wid & 1;
    const int wn = wid >> 1;
    const int gid = lane >> 2;
    const int tig = lane & 3;

    // ldmatrix lane address components (relative to tile bases)
    const uint32_t offA = (uint32_t)((wm * 64 + (lane & 15)) * ROWB + (lane >> 4) * 16);
    const uint32_t offB0 = (uint32_t)((wn * 32 + (lane & 7) + ((lane >> 4) & 1) * 8) * 80
                                      + ((lane >> 3) & 1) * 16);            // mode0
    const uint32_t offB1 = (uint32_t)(((lane & 7) + 8 * ((lane >> 3) & 1)) * 272
                                      + (wn * 32 + ((lane >> 4) & 1) * 8) * 2); // mode1

    float acc[4][4][4];
#pragma unroll
    for (int i = 0; i < 4; i++)
#pragma unroll
        for (int j = 0; j < 4; j++)
#pragma unroll
            for (int k = 0; k < 4; k++) acc[i][j][k] = 0.0f;

    float4 ar[4], br[4];

    auto loadA = [&](int kc) {
#pragma unroll
        for (int i = 0; i < 4; ++i) {
            int v = i * 256 + tid;
            int row = v >> 3, q = v & 7;
            int m = m0 + row;
            ar[i] = make_float4(0.f, 0.f, 0.f, 0.f);
            if (m < M_real)
                ar[i] = *(const float4*)(A + (long long)m * lda + kc + q * 4);
        }
    };
    auto loadB = [&](int kc) {
        if (BMODE == 0) {
#pragma unroll
            for (int i = 0; i < 4; ++i) {
                int v = i * 256 + tid;
                int row = v >> 3, q = v & 7;
                int n = n0 + row;
                br[i] = make_float4(0.f, 0.f, 0.f, 0.f);
                if (n < N_real)
                    br[i] = *(const float4*)(Bg + (long long)n * ldb + kc + q * 4);
            }
        } else {
#pragma unroll
            for (int i = 0; i < 4; ++i) {
                int v = i * 256 + tid;
                int r = v >> 5, c4 = v & 31;
                br[i] = *(const float4*)(Bg + (long long)(kc + r) * ldb + n0 + c4 * 4);
            }
        }
    };
    auto storeTiles = [&](int buf) {
        char* base = smem + buf * BUFSZ;
#pragma unroll
        for (int i = 0; i < 4; ++i) {
            int v = i * 256 + tid;
            int row = v >> 3, q = v & 7;
            uint2 h, l;
            cvt4(ar[i], h, l);
            *(uint2*)(base + row * ROWB + q * 8) = h;
            *(uint2*)(base + ATILE + row * ROWB + q * 8) = l;
        }
        if (BMODE == 0) {
#pragma unroll
            for (int i = 0; i < 4; ++i) {
                int v = i * 256 + tid;
                int row = v >> 3, q = v & 7;
                uint2 h, l;
                cvt4(br[i], h, l);
                *(uint2*)(base + 2 * ATILE + row * 80 + q * 8) = h;
                *(uint2*)(base + 2 * ATILE + BTILE + row * 80 + q * 8) = l;
            }
        } else {
#pragma unroll
            for (int i = 0; i < 4; ++i) {
                int v = i * 256 + tid;
                int r = v >> 5, c4 = v & 31;
                uint2 h, l;
                cvt4(br[i], h, l);
                *(uint2*)(base + 2 * ATILE + r * 272 + c4 * 8) = h;
                *(uint2*)(base + 2 * ATILE + BTILE + r * 272 + c4 * 8) = l;
            }
        }
    };

    const int nchunks = K >> 5;
    loadA(0);
    loadB(0);

#pragma unroll 1
    for (int c = 0; c < nchunks; ++c) {
        const int buf = c & 1;
        storeTiles(buf);
        __syncthreads();

        if (c + 1 < nchunks) {
            loadA((c + 1) << 5);
            loadB((c + 1) << 5);
        }

        const uint32_t tbase = sb + buf * BUFSZ;
        const uint32_t pAhi = tbase + offA;
        const uint32_t pAlo = pAhi + ATILE;

#pragma unroll
        for (int ks = 0; ks < 2; ++ks) {
            uint32_t ahi[4][4], alo[4][4];
#pragma unroll
            for (int mi = 0; mi < 4; ++mi) {
                ldmx4(ahi[mi], pAhi + mi * (16 * ROWB) + ks * 32);
                ldmx4(alo[mi], pAlo + mi * (16 * ROWB) + ks * 32);
            }
            uint32_t bh[4][2], bl[4][2];
            if (BMODE == 0) {
                const uint32_t pBhi = tbase + 2 * ATILE + offB0;
                const uint32_t pBlo = pBhi + BTILE;
#pragma unroll
                for (int g = 0; g < 2; ++g) {
                    uint32_t t[4];
                    ldmx4(t, pBhi + g * (16 * 80) + ks * 32);
                    bh[2 * g][0] = t[0]; bh[2 * g][1] = t[1];
                    bh[2 * g + 1][0] = t[2]; bh[2 * g + 1][1] = t[3];
                    ldmx4(t, pBlo + g * (16 * 80) + ks * 32);
                    bl[2 * g][0] = t[0]; bl[2 * g][1] = t[1];
                    bl[2 * g + 1][0] = t[2]; bl[2 * g + 1][1] = t[3];
                }
            } else {
                const uint32_t pBhi = tbase + 2 * ATILE + offB1 + ks * (16 * 272);
                const uint32_t pBlo = pBhi + BTILE;
#pragma unroll
                for (int g = 0; g < 2; ++g) {
                    uint32_t t[4];
                    ldmx4t(t, pBhi + g * 32);
                    bh[2 * g][0] = t[0]; bh[2 * g][1] = t[1];
                    bh[2 * g + 1][0] = t[2]; bh[2 * g + 1][1] = t[3];
                    ldmx4t(t, pBlo + g * 32);
                    bl[2 * g][0] = t[0]; bl[2 * g][1] = t[1];
                    bl[2 * g + 1][0] = t[2]; bl[2 * g + 1][1] = t[3];
                }
            }
#pragma unroll
            for (int mi = 0; mi < 4; ++mi) {
#pragma unroll
                for (int nt = 0; nt < 4; ++nt) {
                    mma16816(acc[mi][nt], ahi[mi], bh[nt][0], bh[nt][1]);
                    mma16816(acc[mi][nt], ahi[mi], bl[nt][0], bl[nt][1]);
                    mma16816(acc[mi][nt], alo[mi], bh[nt][0], bh[nt][1]);
                }
            }
        }
        // single barrier per chunk: next iteration's convert targets the other
        // buffer; passing this iteration's barrier implies mma(c-1) finished.
    }

    // ---- Epilogue
#pragma unroll
    for (int mi = 0; mi < 4; ++mi) {
#pragma unroll
        for (int nt = 0; nt < 4; ++nt) {
            int r0 = m0 + wm * 64 + mi * 16 + gid;
            int cb = n0 + wn * 32 + nt * 8 + tig * 2;
#pragma unroll
            for (int half = 0; half < 2; ++half) {
                int r = r0 + half * 8;
                if (r < M_real) {
                    float v0 = acc[mi][nt][half * 2 + 0];
                    float v1 = acc[mi][nt][half * 2 + 1];
                    if (cb < N_real) {
                        float o = v0;
                        if (HAS_BIAS) o += bias[cb];
                        C[(long long)r * ldc + cb] = o;
                    }
                    if (cb + 1 < N_real) {
                        float o = v1;
                        if (HAS_BIAS) o += bias[cb + 1];
                        C[(long long)r * ldc + cb + 1] = o;
                    }
                }
            }
        }
    }
}

// ---------------------------------------------------------------------------
// Softmax over 1024 contiguous elements per row; one block per row.
// ---------------------------------------------------------------------------
__global__ __launch_bounds__(256)
void softmax1024(float* __restrict__ data)
{
    const long long row = blockIdx.x;
    float* p = data + row * 1024;
    const int tid = threadIdx.x;

    float4 v = ((const float4*)p)[tid];
    float mx = fmaxf(fmaxf(v.x, v.y), fmaxf(v.z, v.w));
#pragma unroll
    for (int o = 16; o > 0; o >>= 1)
        mx = fmaxf(mx, __shfl_xor_sync(0xffffffffu, mx, o));

    __shared__ float red[8];
    if ((tid & 31) == 0) red[tid >> 5] = mx;
    __syncthreads();
    float mall = red[0];
#pragma unroll
    for (int i = 1; i < 8; i++) mall = fmaxf(mall, red[i]);
    __syncthreads();

    float4 e;
    e.x = expf(v.x - mall); e.y = expf(v.y - mall);
    e.z = expf(v.z - mall); e.w = expf(v.w - mall);

    float s = e.x + e.y + e.z + e.w;
#pragma unroll
    for (int o = 16; o > 0; o >>= 1)
        s += __shfl_xor_sync(0xffffffffu, s, o);
    if ((tid & 31) == 0) red[tid >> 5] = s;
    __syncthreads();
    float sall = 0.0f;
#pragma unroll
    for (int i = 0; i < 8; i++) sall += red[i];

    float inv = 1.0f / sall;
    e.x *= inv; e.y *= inv; e.z *= inv; e.w *= inv;
    ((float4*)p)[tid] = e;
}

// ---------------------------------------------------------------------------
extern "C" void kernel_launch(void* const* d_in, const int* in_sizes, int n_in,
                              void* d_out, int out_size)
{
    const float* pf   = (const float*)d_in[0];  // position_fmap [B, L, H]
    const float* of   = (const float*)d_in[1];  // origin_fmap   [B, L, H]
    const float* emb  = (const float*)d_in[2];  // pos_emb       [T, H]
    const float* W    = (const float*)d_in[3];  // W_gen         [C, H]
    const float* bias = (const float*)d_in[4];  // b_gen         [C]
    float* out = (float*)d_out;                 // [B, T, C]

    float* scores = nullptr;
    float* context = nullptr;
    cudaGetSymbolAddress((void**)&scores, g_scores);
    cudaGetSymbolAddress((void**)&context, g_context);

    constexpr int SMEM0 = 2 * (2 * 128 * 80 + 2 * 128 * 80);   // 81920
    constexpr int SMEM1 = 2 * (2 * 128 * 80 + 2 * 32 * 272);   // 75776
    cudaFuncSetAttribute((const void*)hmma_gemm<0, false>,
                         cudaFuncAttributeMaxDynamicSharedMemorySize, SMEM0);
    cudaFuncSetAttribute((const void*)hmma_gemm<1, false>,
                         cudaFuncAttributeMaxDynamicSharedMemorySize, SMEM1);
    cudaFuncSetAttribute((const void*)hmma_gemm<0, true>,
                         cudaFuncAttributeMaxDynamicSharedMemorySize, SMEM0);

    // K1: scores[b, t, l] = sum_h emb[t, h] * pf[b, l, h]
    {
        dim3 grid(Ll / 128, 1, Bb);
        hmma_gemm<0, false><<<grid, 256, SMEM0>>>(
            emb, pf, scores, nullptr,
            Tt, Ll, Hh,
            Hh, Hh, Ll,
            0LL, (long long)Ll * Hh, (long long)Tt * Ll);
    }

    // K2: softmax over L per (b, t) row
    softmax1024<<<Bb * Tt, 256>>>(scores);

    // K3: context[b, t, h] = sum_l attn[b, t, l] * of[b, l, h]
    //     B = of[b] is [k=l, n=h] row-major -> BMODE 1 (ldmatrix.trans)
    {
        dim3 grid(Hh / 128, 1, Bb);
        hmma_gemm<1, false><<<grid, 256, SMEM1>>>(
            scores, of, context, nullptr,
            Tt, Hh, Ll,
            Ll, Hh, Hh,
            (long long)Tt * Ll, (long long)Ll * Hh, (long long)Tt * Hh);
    }

    // K4: out[bt, c] = sum_h context[bt, h] * W[c, h] + bias[c]
    {
        dim3 grid(1, (Bb * Tt) / 128, 1);
        hmma_gemm<0, true><<<grid, 256, SMEM0>>>(
            context, W, out, bias,
            Bb * Tt, Cc, Hh,
            Hh, Hh, Cc,
            0LL, 0LL, 0LL);
    }
}